// round 6
// baseline (speedup 1.0000x reference)
#include <cuda_runtime.h>
#include <cuda_fp16.h>
#include <cstdint>
#include <math.h>

// Problem constants
#define BB   4
#define SS   2048
#define DD   1024
#define HH   16
#define HDIM 64

// Scratch (allocation-free rule: __device__ globals)
__device__ __half g_Qh [(size_t)8192 * 1024];      // fp16 single
__device__ __half g_Kh [(size_t)8192 * 1024];      // fp16 single
__device__ __half g_Vhi[(size_t)8192 * 1024];
__device__ __half g_Vlo[(size_t)8192 * 1024];
__device__ __half g_Xhi[(size_t)8192 * 1024];
__device__ __half g_Xlo[(size_t)8192 * 1024];
// Pre-split activations (x + posemb) for q/k/v projections
__device__ __half g_Ahi[3][(size_t)8192 * 1024];
__device__ __half g_Alo[3][(size_t)8192 * 1024];
// Pre-transposed + fp16-split weights: [4][N=1024][K=1024]
__device__ __half g_Whi[4][(size_t)1024 * 1024];
__device__ __half g_Wlo[4][(size_t)1024 * 1024];

// ---------------------------------------------------------------------------
// Helpers
// ---------------------------------------------------------------------------
__device__ __forceinline__ uint32_t smem_u32(const void* p) {
    uint32_t a;
    asm("{ .reg .u64 t; cvta.to.shared.u64 t, %1; cvt.u32.u64 %0, t; }" : "=r"(a) : "l"(p));
    return a;
}
__device__ __forceinline__ void ldm4(uint32_t* r, uint32_t addr) {
    asm volatile("ldmatrix.sync.aligned.m8n8.x4.shared.b16 {%0,%1,%2,%3}, [%4];"
                 : "=r"(r[0]), "=r"(r[1]), "=r"(r[2]), "=r"(r[3]) : "r"(addr));
}
__device__ __forceinline__ void ldm4t(uint32_t* r, uint32_t addr) {
    asm volatile("ldmatrix.sync.aligned.m8n8.x4.trans.shared.b16 {%0,%1,%2,%3}, [%4];"
                 : "=r"(r[0]), "=r"(r[1]), "=r"(r[2]), "=r"(r[3]) : "r"(addr));
}
__device__ __forceinline__ void mma_f16(float* c, const uint32_t* a, uint32_t b0, uint32_t b1) {
    asm volatile(
        "mma.sync.aligned.m16n8k16.row.col.f32.f16.f16.f32 "
        "{%0,%1,%2,%3}, {%4,%5,%6,%7}, {%8,%9}, {%0,%1,%2,%3};"
        : "+f"(c[0]), "+f"(c[1]), "+f"(c[2]), "+f"(c[3])
        : "r"(a[0]), "r"(a[1]), "r"(a[2]), "r"(a[3]), "r"(b0), "r"(b1));
}
__device__ __forceinline__ uint32_t pack2h(__half a, __half b) {
    __half2 t = __halves2half2(a, b);
    return *(uint32_t*)&t;
}
__device__ __forceinline__ void cp16(uint32_t dst, const void* src) {
    asm volatile("cp.async.cg.shared.global [%0], [%1], 16;" :: "r"(dst), "l"(src));
}
#define CP_COMMIT() asm volatile("cp.async.commit_group;" ::: "memory")
#define CP_WAIT(N)  asm volatile("cp.async.wait_group %0;" :: "n"(N) : "memory")

// ---------------------------------------------------------------------------
// Prep 1: transpose W[K][N] -> [N][K], split into fp16 hi/lo
// ---------------------------------------------------------------------------
__global__ void prep_w_kernel(const float* __restrict__ W,
                              __half* __restrict__ Whi, __half* __restrict__ Wlo)
{
    __shared__ float t[32][33];
    const int n0 = blockIdx.x * 32, k0 = blockIdx.y * 32;
    const int tx = threadIdx.x, ty = threadIdx.y;
#pragma unroll
    for (int i = 0; i < 4; ++i)
        t[ty + i * 8][tx] = W[(size_t)(k0 + ty + i * 8) * 1024 + n0 + tx];
    __syncthreads();
#pragma unroll
    for (int i = 0; i < 4; ++i) {
        int n = n0 + ty + i * 8;
        float x = t[tx][ty + i * 8];
        __half h = __float2half_rn(x);
        Whi[(size_t)n * 1024 + k0 + tx] = h;
        Wlo[(size_t)n * 1024 + k0 + tx] = __float2half_rn(x - __half2float(h));
    }
}

// ---------------------------------------------------------------------------
// Prep 2: activations: split(x + pos_{q,k,v}) -> fp16 hi/lo, 3 targets
// ---------------------------------------------------------------------------
__global__ __launch_bounds__(256)
void prep_act_kernel(const float* __restrict__ x, const float* __restrict__ pq,
                     const float* __restrict__ pk, const float* __restrict__ pv)
{
    const size_t base = ((size_t)blockIdx.x * 256 + threadIdx.x) * 4;
    const size_t poff = base & ((size_t)SS * 1024 - 1);
    float4 xv = *(const float4*)(x + base);
    const float* ptab[3] = {pq, pk, pv};
#pragma unroll
    for (int t = 0; t < 3; ++t) {
        float4 pv4 = *(const float4*)(ptab[t] + poff);
        float v[4] = {xv.x + pv4.x, xv.y + pv4.y, xv.z + pv4.z, xv.w + pv4.w};
        __half h[4]; uint32_t hi[2], lo[2];
#pragma unroll
        for (int j = 0; j < 4; ++j) h[j] = __float2half_rn(v[j]);
        hi[0] = pack2h(h[0], h[1]); hi[1] = pack2h(h[2], h[3]);
        lo[0] = pack2h(__float2half_rn(v[0] - __half2float(h[0])),
                       __float2half_rn(v[1] - __half2float(h[1])));
        lo[1] = pack2h(__float2half_rn(v[2] - __half2float(h[2])),
                       __float2half_rn(v[3] - __half2float(h[3])));
        *(uint2*)(&g_Ahi[t][base]) = make_uint2(hi[0], hi[1]);
        *(uint2*)(&g_Alo[t][base]) = make_uint2(lo[0], lo[1]);
    }
}

// ---------------------------------------------------------------------------
// fp16 3-term GEMM, cp.async 4-stage pipeline.
// C = (Ahi+Alo) @ (Whi+Wlo)^T + bias, scaled. Output: fp32 C | fp16 Chi[+Clo].
// ---------------------------------------------------------------------------
#define ROWB   80
#define AHI_O  0
#define ALO_O  10240
#define BHI_O  20480
#define BLO_O  30720
#define STAGEB 40960
#define GEMM_SMEM_BYTES (4 * STAGEB)

__global__ __launch_bounds__(512, 1)
void gemm_mma_kernel(const __half* __restrict__ Ahi, const __half* __restrict__ Alo,
                     const __half* __restrict__ Bhi, const __half* __restrict__ Blo,
                     const float* __restrict__ bias, float* __restrict__ C,
                     __half* __restrict__ Chi, __half* __restrict__ Clo, float scale)
{
    extern __shared__ char sm[];
    const uint32_t sb = smem_u32(sm);

    const int tid = threadIdx.x, lane = tid & 31, wid = tid >> 5;
    const int m0 = blockIdx.y * 128, n0 = blockIdx.x * 128;
    const int wm = (wid & 3) * 32, wn = (wid >> 2) * 32;
    const int grp = lane >> 2, qid = lane & 3;
    const int lm_off = (lane & 15) * ROWB + ((lane >> 4) << 4);
    const int p_row = tid >> 2, p_ch = tid & 3;    // producer: 128 rows x 4 chunks16B

    float acc[2][4][4];
#pragma unroll
    for (int t = 0; t < 2; ++t)
#pragma unroll
        for (int u = 0; u < 4; ++u)
#pragma unroll
            for (int v = 0; v < 4; ++v) acc[t][u][v] = 0.f;

    auto issue_chunk = [&](int c) {
        const uint32_t st = sb + (c & 3) * STAGEB;
        const uint32_t so = p_row * ROWB + p_ch * 16;
        const size_t ga = (size_t)(m0 + p_row) * 1024 + c * 32 + p_ch * 8;
        const size_t gb = (size_t)(n0 + p_row) * 1024 + c * 32 + p_ch * 8;
        cp16(st + AHI_O + so, Ahi + ga);
        cp16(st + ALO_O + so, Alo + ga);
        cp16(st + BHI_O + so, Bhi + gb);
        cp16(st + BLO_O + so, Blo + gb);
    };

    issue_chunk(0); CP_COMMIT();
    issue_chunk(1); CP_COMMIT();
    issue_chunk(2); CP_COMMIT();

    for (int c = 0; c < 32; ++c) {
        CP_WAIT(2);
        __syncthreads();
        if (c + 3 < 32) issue_chunk(c + 3);
        CP_COMMIT();

        const uint32_t sbase = sb + (c & 3) * STAGEB;
#pragma unroll
        for (int ks = 0; ks < 2; ++ks) {
            const uint32_t ko = ks * 32;
            uint32_t ah[2][4], al[2][4], bh[2][4], bl[2][4];
#pragma unroll
            for (int t = 0; t < 2; ++t) {
                uint32_t ra = (wm + t * 16) * ROWB + lm_off + ko;
                ldm4(ah[t], sbase + AHI_O + ra);
                ldm4(al[t], sbase + ALO_O + ra);
            }
#pragma unroll
            for (int p = 0; p < 2; ++p) {
                uint32_t rb = (wn + p * 16) * ROWB + lm_off + ko;
                ldm4(bh[p], sbase + BHI_O + rb);
                ldm4(bl[p], sbase + BLO_O + rb);
            }
#pragma unroll
            for (int t = 0; t < 2; ++t)
#pragma unroll
                for (int p = 0; p < 2; ++p) {
                    mma_f16(acc[t][p * 2 + 0], ah[t], bh[p][0], bh[p][2]);
                    mma_f16(acc[t][p * 2 + 1], ah[t], bh[p][1], bh[p][3]);
                    mma_f16(acc[t][p * 2 + 0], ah[t], bl[p][0], bl[p][2]);
                    mma_f16(acc[t][p * 2 + 1], ah[t], bl[p][1], bl[p][3]);
                    mma_f16(acc[t][p * 2 + 0], al[t], bh[p][0], bh[p][2]);
                    mma_f16(acc[t][p * 2 + 1], al[t], bh[p][1], bh[p][3]);
                }
        }
        __syncthreads();    // all warps done with stage c before it is refilled
    }

    // Epilogue
#pragma unroll
    for (int t = 0; t < 2; ++t) {
        const int r0 = m0 + wm + t * 16 + grp;
#pragma unroll
        for (int u = 0; u < 4; ++u) {
            const int col = n0 + wn + u * 8 + qid * 2;
            const float b0v = bias[col], b1v = bias[col + 1];
            float v00 = (acc[t][u][0] + b0v) * scale;
            float v01 = (acc[t][u][1] + b1v) * scale;
            float v10 = (acc[t][u][2] + b0v) * scale;
            float v11 = (acc[t][u][3] + b1v) * scale;
            if (Chi) {
                __half h00 = __float2half_rn(v00), h01 = __float2half_rn(v01);
                __half h10 = __float2half_rn(v10), h11 = __float2half_rn(v11);
                *(uint32_t*)(Chi + (size_t)r0 * 1024 + col) = pack2h(h00, h01);
                *(uint32_t*)(Chi + (size_t)(r0 + 8) * 1024 + col) = pack2h(h10, h11);
                if (Clo) {
                    *(uint32_t*)(Clo + (size_t)r0 * 1024 + col) =
                        pack2h(__float2half_rn(v00 - __half2float(h00)),
                               __float2half_rn(v01 - __half2float(h01)));
                    *(uint32_t*)(Clo + (size_t)(r0 + 8) * 1024 + col) =
                        pack2h(__float2half_rn(v10 - __half2float(h10)),
                               __float2half_rn(v11 - __half2float(h11)));
                }
            } else {
                float2 o0 = {v00, v01}, o1 = {v10, v11};
                *(float2*)(C + (size_t)r0 * 1024 + col) = o0;
                *(float2*)(C + (size_t)(r0 + 8) * 1024 + col) = o1;
            }
        }
    }
}

// ---------------------------------------------------------------------------
// Flash attention: fp16-single QK^T, fp16-single P x split-fp16 V.
// 256 threads = 8 warps; warp w owns rows 16w..16w+15 of a 128-row q-tile.
// ---------------------------------------------------------------------------
#define AROWB  144
#define A_Q    0
#define A_ST0  18432
#define A_STB  27648                    // K + Vhi + Vlo, 64 x 144 each
#define A_K    0
#define A_VHI  9216
#define A_VLO  18432
#define ATTN_SMEM_BYTES (A_ST0 + 2 * A_STB)

__global__ __launch_bounds__(256)
void attn_mma_kernel(const float* __restrict__ ab, const float* __restrict__ abkv)
{
    extern __shared__ char sm[];
    const uint32_t sb = smem_u32(sm);
    const int tid = threadIdx.x, lane = tid & 31, wid = tid >> 5;
    const int grp = lane >> 2, qid = lane & 3;
    const int b = blockIdx.z, h = blockIdx.y, q0 = blockIdx.x * 128;
    const int wr = wid * 16;
    const int lm_off = (lane & 15) * AROWB + ((lane >> 4) << 4);

    // Q tile: 128 x 64 fp16 = 1024 x 16B
#pragma unroll
    for (int i = 0; i < 4; ++i) {
        int idx = i * 256 + tid;
        int row = idx >> 3, ch = idx & 7;
        cp16(sb + A_Q + row * AROWB + ch * 16,
             g_Qh + (size_t)(b * SS + q0 + row) * 1024 + h * 64 + ch * 8);
    }

    auto issue_tile = [&](int kt) {
        const uint32_t st = sb + A_ST0 + (kt & 1) * A_STB;
        const int k0 = kt * 64;
#pragma unroll
        for (int i = 0; i < 6; ++i) {
            int idx = i * 256 + tid;                 // 0..1535
            int arr = idx >> 9;                      // 0=K 1=Vhi 2=Vlo
            int rem = idx & 511;
            int row = rem >> 3, ch = rem & 7;
            const __half* g = (arr == 0 ? g_Kh : arr == 1 ? g_Vhi : g_Vlo)
                + (size_t)(b * SS + k0 + row) * 1024 + h * 64 + ch * 8;
            cp16(st + (arr == 0 ? A_K : arr == 1 ? A_VHI : A_VLO) + row * AROWB + ch * 16, g);
        }
    };

    issue_tile(0); CP_COMMIT();     // G0 = Q + tile0
    issue_tile(1); CP_COMMIT();     // G1
    CP_WAIT(1);
    __syncthreads();

    // Q fragments
    uint32_t qf[4][4];
#pragma unroll
    for (int ks = 0; ks < 4; ++ks)
        ldm4(qf[ks], sb + A_Q + wr * AROWB + lm_off + ks * 32);

    float oacc[8][4];
#pragma unroll
    for (int f = 0; f < 8; ++f)
#pragma unroll
        for (int v = 0; v < 4; ++v) oacc[f][v] = 0.f;
    float m0 = -1e30f, m1 = -1e30f, l0 = 0.f, l1 = 0.f;

    const float* abp   = ab + (size_t)(q0 + wr + grp) * SS + qid * 2;
    const float* abkvp = abkv + b * SS + qid * 2;

    for (int kt = 0; kt < 32; ++kt) {
        const uint32_t st = sb + A_ST0 + (kt & 1) * A_STB;
        const int k0 = kt * 64;

        CP_WAIT(1);
        __syncthreads();

        // ---- S = Q K^T (1-term fp16) ----
        float sacc[8][4];
#pragma unroll
        for (int f = 0; f < 8; ++f)
#pragma unroll
            for (int v = 0; v < 4; ++v) sacc[f][v] = 0.f;

#pragma unroll
        for (int ks = 0; ks < 4; ++ks) {
            uint32_t kh[4][4];
#pragma unroll
            for (int j = 0; j < 4; ++j)
                ldm4(kh[j], st + A_K + (j * 16) * AROWB + lm_off + ks * 32);
#pragma unroll
            for (int j = 0; j < 4; ++j) {
                mma_f16(sacc[2 * j + 0], qf[ks], kh[j][0], kh[j][2]);
                mma_f16(sacc[2 * j + 1], qf[ks], kh[j][1], kh[j][3]);
            }
        }

        // ---- bias + online softmax ----
        float mx0 = -1e30f, mx1 = -1e30f;
#pragma unroll
        for (int f = 0; f < 8; ++f) {
            float2 bk = *(const float2*)(abkvp + k0 + f * 8);
            float2 b0 = *(const float2*)(abp + k0 + f * 8);
            float2 b1 = *(const float2*)(abp + 8 * SS + k0 + f * 8);
            sacc[f][0] += b0.x + bk.x; sacc[f][1] += b0.y + bk.y;
            sacc[f][2] += b1.x + bk.x; sacc[f][3] += b1.y + bk.y;
            mx0 = fmaxf(mx0, fmaxf(sacc[f][0], sacc[f][1]));
            mx1 = fmaxf(mx1, fmaxf(sacc[f][2], sacc[f][3]));
        }
        mx0 = fmaxf(mx0, __shfl_xor_sync(0xffffffffu, mx0, 1));
        mx0 = fmaxf(mx0, __shfl_xor_sync(0xffffffffu, mx0, 2));
        mx1 = fmaxf(mx1, __shfl_xor_sync(0xffffffffu, mx1, 1));
        mx1 = fmaxf(mx1, __shfl_xor_sync(0xffffffffu, mx1, 2));

        const float mn0 = fmaxf(m0, mx0), mn1 = fmaxf(m1, mx1);
        const float e0 = __expf(m0 - mn0), e1 = __expf(m1 - mn1);
        m0 = mn0; m1 = mn1;

        float rs0 = 0.f, rs1 = 0.f;
        uint32_t aP[4][4];
#pragma unroll
        for (int j = 0; j < 4; ++j) {
            float p[8];
            p[0] = __expf(sacc[2 * j][0] - mn0);
            p[1] = __expf(sacc[2 * j][1] - mn0);
            p[2] = __expf(sacc[2 * j][2] - mn1);
            p[3] = __expf(sacc[2 * j][3] - mn1);
            p[4] = __expf(sacc[2 * j + 1][0] - mn0);
            p[5] = __expf(sacc[2 * j + 1][1] - mn0);
            p[6] = __expf(sacc[2 * j + 1][2] - mn1);
            p[7] = __expf(sacc[2 * j + 1][3] - mn1);
            rs0 += p[0] + p[1] + p[4] + p[5];
            rs1 += p[2] + p[3] + p[6] + p[7];
            aP[j][0] = pack2h(__float2half_rn(p[0]), __float2half_rn(p[1]));
            aP[j][1] = pack2h(__float2half_rn(p[2]), __float2half_rn(p[3]));
            aP[j][2] = pack2h(__float2half_rn(p[4]), __float2half_rn(p[5]));
            aP[j][3] = pack2h(__float2half_rn(p[6]), __float2half_rn(p[7]));
        }
        l0 = l0 * e0 + rs0;
        l1 = l1 * e1 + rs1;
#pragma unroll
        for (int f = 0; f < 8; ++f) {
            oacc[f][0] *= e0; oacc[f][1] *= e0;
            oacc[f][2] *= e1; oacc[f][3] *= e1;
        }

        // ---- O += P (Vhi + Vlo) ----
#pragma unroll
        for (int j = 0; j < 4; ++j) {
            uint32_t vh[4][4], vl[4][4];
#pragma unroll
            for (int jj = 0; jj < 4; ++jj) {
                uint32_t rb = (j * 16 + (lane & 15)) * AROWB + jj * 32 + ((lane >> 4) << 4);
                ldm4t(vh[jj], st + A_VHI + rb);
                ldm4t(vl[jj], st + A_VLO + rb);
            }
#pragma unroll
            for (int jj = 0; jj < 4; ++jj) {
                mma_f16(oacc[2 * jj + 0], aP[j], vh[jj][0], vh[jj][1]);
                mma_f16(oacc[2 * jj + 1], aP[j], vh[jj][2], vh[jj][3]);
                mma_f16(oacc[2 * jj + 0], aP[j], vl[jj][0], vl[jj][1]);
                mma_f16(oacc[2 * jj + 1], aP[j], vl[jj][2], vl[jj][3]);
            }
        }

        __syncthreads();
        if (kt + 2 < 32) issue_tile(kt + 2);
        CP_COMMIT();
    }

    // ---- normalize + write split-fp16 X ----
    l0 += __shfl_xor_sync(0xffffffffu, l0, 1);
    l0 += __shfl_xor_sync(0xffffffffu, l0, 2);
    l1 += __shfl_xor_sync(0xffffffffu, l1, 1);
    l1 += __shfl_xor_sync(0xffffffffu, l1, 2);
    const float inv0 = 1.f / l0, inv1 = 1.f / l1;

    const size_t xo = (size_t)(b * SS + q0 + wr + grp) * 1024 + h * 64 + qid * 2;
#pragma unroll
    for (int f = 0; f < 8; ++f) {
        float v00 = oacc[f][0] * inv0, v01 = oacc[f][1] * inv0;
        float v10 = oacc[f][2] * inv1, v11 = oacc[f][3] * inv1;
        __half h00 = __float2half_rn(v00), h01 = __float2half_rn(v01);
        __half h10 = __float2half_rn(v10), h11 = __float2half_rn(v11);
        *(uint32_t*)(g_Xhi + xo + f * 8) = pack2h(h00, h01);
        *(uint32_t*)(g_Xhi + xo + (size_t)8 * 1024 + f * 8) = pack2h(h10, h11);
        *(uint32_t*)(g_Xlo + xo + f * 8) =
            pack2h(__float2half_rn(v00 - __half2float(h00)),
                   __float2half_rn(v01 - __half2float(h01)));
        *(uint32_t*)(g_Xlo + xo + (size_t)8 * 1024 + f * 8) =
            pack2h(__float2half_rn(v10 - __half2float(h10)),
                   __float2half_rn(v11 - __half2float(h11)));
    }
}

// ---------------------------------------------------------------------------
extern "C" void kernel_launch(void* const* d_in, const int* in_sizes, int n_in,
                              void* d_out, int out_size)
{
    const float* x    = (const float*)d_in[0];
    const float* pq   = (const float*)d_in[1];
    const float* pk   = (const float*)d_in[2];
    const float* pv   = (const float*)d_in[3];
    const float* ab   = (const float*)d_in[4];
    const float* abkv = (const float*)d_in[5];
    const float* bq   = (const float*)d_in[7];
    const float* bk   = (const float*)d_in[9];
    const float* bv   = (const float*)d_in[11];
    const float* wo   = (const float*)d_in[12];
    const float* bo   = (const float*)d_in[13];
    const float* wq   = (const float*)d_in[6];
    const float* wk   = (const float*)d_in[8];
    const float* wv   = (const float*)d_in[10];
    float* out = (float*)d_out;

    __half *Whi, *Wlo, *Ahi, *Alo, *Qh, *Kh, *Vhi, *Vlo, *Xhi, *Xlo;
    cudaGetSymbolAddress((void**)&Whi, g_Whi);
    cudaGetSymbolAddress((void**)&Wlo, g_Wlo);
    cudaGetSymbolAddress((void**)&Ahi, g_Ahi);
    cudaGetSymbolAddress((void**)&Alo, g_Alo);
    cudaGetSymbolAddress((void**)&Qh,  g_Qh);
    cudaGetSymbolAddress((void**)&Kh,  g_Kh);
    cudaGetSymbolAddress((void**)&Vhi, g_Vhi);
    cudaGetSymbolAddress((void**)&Vlo, g_Vlo);
    cudaGetSymbolAddress((void**)&Xhi, g_Xhi);
    cudaGetSymbolAddress((void**)&Xlo, g_Xlo);
    const size_t WSZ = (size_t)1024 * 1024;
    const size_t ASZ = (size_t)8192 * 1024;

    dim3 pgrid(32, 32), pblk(32, 8);
    prep_w_kernel<<<pgrid, pblk>>>(wq, Whi + 0 * WSZ, Wlo + 0 * WSZ);
    prep_w_kernel<<<pgrid, pblk>>>(wk, Whi + 1 * WSZ, Wlo + 1 * WSZ);
    prep_w_kernel<<<pgrid, pblk>>>(wv, Whi + 2 * WSZ, Wlo + 2 * WSZ);
    prep_w_kernel<<<pgrid, pblk>>>(wo, Whi + 3 * WSZ, Wlo + 3 * WSZ);
    prep_act_kernel<<<8192, 256>>>(x, pq, pk, pv);

    cudaFuncSetAttribute(gemm_mma_kernel, cudaFuncAttributeMaxDynamicSharedMemorySize,
                         GEMM_SMEM_BYTES);
    dim3 ggrid(1024 / 128, 8192 / 128);

    // Q: fp16 single (scale 1/8). K: fp16 single. V: fp16 split.
    gemm_mma_kernel<<<ggrid, 512, GEMM_SMEM_BYTES>>>(Ahi + 0 * ASZ, Alo + 0 * ASZ,
        Whi + 0 * WSZ, Wlo + 0 * WSZ, bq, nullptr, Qh, nullptr, 0.125f);
    gemm_mma_kernel<<<ggrid, 512, GEMM_SMEM_BYTES>>>(Ahi + 1 * ASZ, Alo + 1 * ASZ,
        Whi + 1 * WSZ, Wlo + 1 * WSZ, bk, nullptr, Kh, nullptr, 1.0f);
    gemm_mma_kernel<<<ggrid, 512, GEMM_SMEM_BYTES>>>(Ahi + 2 * ASZ, Alo + 2 * ASZ,
        Whi + 2 * WSZ, Wlo + 2 * WSZ, bv, nullptr, Vhi, Vlo, 1.0f);

    cudaFuncSetAttribute(attn_mma_kernel, cudaFuncAttributeMaxDynamicSharedMemorySize,
                         ATTN_SMEM_BYTES);
    attn_mma_kernel<<<dim3(SS / 128, HH, BB), 256, ATTN_SMEM_BYTES>>>(ab, abkv);

    gemm_mma_kernel<<<ggrid, 512, GEMM_SMEM_BYTES>>>(Xhi, Xlo,
        Whi + 3 * WSZ, Wlo + 3 * WSZ, bo, out, nullptr, nullptr, 1.0f);
}